// round 16
// baseline (speedup 1.0000x reference)
#include <cuda_runtime.h>
#include <cuda_bf16.h>

// GANLoss: out = -mean(prob[n, targets[n]] * reward[n]), N=8192, C=32000.
// PDL two-kernel, minimal producer critical path:
//   gather: 256 CTAs x 32 threads (one warp/block). No smem, no syncthreads:
//           gather -> 5 shuffles -> ONE st.release.gpu.u64 {flag|payload}.
//   finalize (PDL, released at gather ENTRY): 256 threads, lane i polls
//           slot i in parallel (no sequential polling), two-stage fixed
//           -order reduce (rel_err 0), store, slot reset for graph replay.

#define NSLOTS    256
#define PROD_THREADS 32
#define FIN_THREADS  256

__device__ unsigned long long g_slots[NSLOTS];   // zero-initialized

__global__ __launch_bounds__(PROD_THREADS) void gather_kernel(
    const float* __restrict__ prob,
    const int* __restrict__ targets,
    const float* __restrict__ reward,
    unsigned int C)
{
    // Release the dependent finalize grid immediately; visibility is via the
    // release/acquire slot protocol.
    cudaTriggerProgrammaticLaunchCompletion();

    const int idx  = blockIdx.x * PROD_THREADS + threadIdx.x;  // < 8192
    const int lane = threadIdx.x;

    unsigned int t = (unsigned int)targets[idx];
    unsigned int off32 = (unsigned int)idx * C + t;            // N*C < 2^31
    float v = __ldg(&prob[off32]) * __ldg(&reward[idx]);

    // warp reduce (5 shuffles) — only reduction stage on the producer side
    #pragma unroll
    for (int off = 16; off > 0; off >>= 1)
        v += __shfl_xor_sync(0xFFFFFFFFu, v, off);

    if (lane == 0) {
        unsigned long long word =
            (1ULL << 63) | (unsigned long long)__float_as_uint(v);
        asm volatile("st.release.gpu.u64 [%0], %1;"
                     :: "l"(&g_slots[blockIdx.x]), "l"(word) : "memory");
    }
}

__global__ __launch_bounds__(FIN_THREADS) void finalize_kernel(
    float* __restrict__ out, float neg_inv_n)
{
    const int tid  = threadIdx.x;
    const int lane = tid & 31;
    const int wid  = tid >> 5;

    // Released early by the gather's entry trigger; each thread polls its
    // own slot — 256 fully parallel spin addresses.
    unsigned long long word;
    do {
        asm volatile("ld.acquire.gpu.u64 %0, [%1];"
                     : "=l"(word) : "l"(&g_slots[tid]) : "memory");
    } while (!(word >> 63));

    float v = __uint_as_float((unsigned int)word);

    #pragma unroll
    for (int off = 16; off > 0; off >>= 1)
        v += __shfl_xor_sync(0xFFFFFFFFu, v, off);

    __shared__ float s_warp[FIN_THREADS / 32];
    if (lane == 0) s_warp[wid] = v;
    __syncthreads();

    if (tid < 32) {
        float w = (lane < FIN_THREADS / 32) ? s_warp[lane] : 0.0f;
        #pragma unroll
        for (int off = 4; off > 0; off >>= 1)
            w += __shfl_xor_sync(0xFFFFFFFFu, w, off);
        if (lane == 0)
            out[0] = w * neg_inv_n;
    }

    // reset slots for the next graph replay (stream-order visible)
    g_slots[tid] = 0ULL;
}

extern "C" void kernel_launch(void* const* d_in, const int* in_sizes, int n_in,
                              void* d_out, int out_size)
{
    const float* prob    = (const float*)d_in[0];
    const int*   targets = (const int*)d_in[1];
    const float* reward  = (const float*)d_in[2];
    float*       out     = (float*)d_out;

    const int N = in_sizes[2];                              // 8192
    const unsigned int C = (unsigned int)(in_sizes[0] / N); // 32000

    gather_kernel<<<NSLOTS, PROD_THREADS>>>(prob, targets, reward, C);

    cudaLaunchConfig_t cfg = {};
    cfg.gridDim  = dim3(1, 1, 1);
    cfg.blockDim = dim3(FIN_THREADS, 1, 1);
    cfg.dynamicSmemBytes = 0;
    cfg.stream = 0;
    cudaLaunchAttribute attr;
    attr.id = cudaLaunchAttributeProgrammaticStreamSerialization;
    attr.val.programmaticStreamSerializationAllowed = 1;
    cfg.attrs = &attr;
    cfg.numAttrs = 1;

    float neg_inv_n = -1.0f / (float)N;
    cudaLaunchKernelEx(&cfg, finalize_kernel, out, neg_inv_n);
}

// round 17
// speedup vs baseline: 1.0433x; 1.0433x over previous
#include <cuda_runtime.h>
#include <cuda_bf16.h>

// GANLoss: out = -mean(prob[n, targets[n]] * reward[n]), N=8192, C=32000.
// TERMINAL: best-measured design (R10, 6.59us), resubmitted verbatim.
// Full-overlap PDL: gather triggers launch-completion at ENTRY, so the
// finalize block is resident while the gather runs. Data dependency is an
// explicit release/acquire handshake: each gather CTA release-increments a
// counter after storing its partial; the finalize acquire-spins until all
// 32 arrive, then does a fixed-order reduction (rel_err 0) and resets the
// counter for the next graph replay.

#define NBLOCKS  32
#define NTHREADS 256

__device__ float g_partials[NBLOCKS];
__device__ int   g_done = 0;

__global__ __launch_bounds__(NTHREADS) void gather_kernel(
    const float* __restrict__ prob,
    const int* __restrict__ targets,
    const float* __restrict__ reward,
    int N, long long C)
{
    // Release the dependent finalize grid immediately: its launch + block
    // dispatch overlap our entire execution. Visibility of our results is
    // handled by the release/acquire counter below, not by PDL.
    cudaTriggerProgrammaticLaunchCompletion();

    int idx = blockIdx.x * blockDim.x + threadIdx.x;

    float v = 0.0f;
    if (idx < N) {
        int t = targets[idx];
        v = __ldg(&prob[(long long)idx * C + (long long)t]) * __ldg(&reward[idx]);
    }

    // warp reduce (5 shuffles)
    #pragma unroll
    for (int off = 16; off > 0; off >>= 1)
        v += __shfl_xor_sync(0xFFFFFFFFu, v, off);

    __shared__ float s_warp[NTHREADS / 32];
    const int lane = threadIdx.x & 31;
    const int wid  = threadIdx.x >> 5;
    if (lane == 0) s_warp[wid] = v;
    __syncthreads();

    if (threadIdx.x < 32) {
        float w = (lane < NTHREADS / 32) ? s_warp[lane] : 0.0f;
        #pragma unroll
        for (int off = 4; off > 0; off >>= 1)
            w += __shfl_xor_sync(0xFFFFFFFFu, w, off);
        if (lane == 0) {
            g_partials[blockIdx.x] = w;
            // release RMW: orders the partial store before the increment
            asm volatile("red.release.gpu.add.s32 [%0], %1;"
                         :: "l"(&g_done), "r"(1) : "memory");
        }
    }
}

__global__ __launch_bounds__(32) void finalize_kernel(
    float* __restrict__ out, float neg_inv_n)
{
    // Released early by the gather's entry trigger; spin until all 32
    // CTAs have release-incremented the counter.
    int c;
    do {
        asm volatile("ld.acquire.gpu.s32 %0, [%1];"
                     : "=r"(c) : "l"(&g_done) : "memory");
    } while (c < NBLOCKS);

    float v = g_partials[threadIdx.x];          // 32 partials, 1 warp
    #pragma unroll
    for (int off = 16; off > 0; off >>= 1)
        v += __shfl_xor_sync(0xFFFFFFFFu, v, off);

    if (threadIdx.x == 0) {
        out[0] = v * neg_inv_n;
        g_done = 0;   // reset for next graph replay (stream-order visible)
    }
}

extern "C" void kernel_launch(void* const* d_in, const int* in_sizes, int n_in,
                              void* d_out, int out_size)
{
    const float* prob    = (const float*)d_in[0];
    const int*   targets = (const int*)d_in[1];
    const float* reward  = (const float*)d_in[2];
    float*       out     = (float*)d_out;

    const int N = in_sizes[2];                       // 8192
    const long long C = (long long)in_sizes[0] / N;  // 32000

    gather_kernel<<<NBLOCKS, NTHREADS>>>(prob, targets, reward, N, C);

    cudaLaunchConfig_t cfg = {};
    cfg.gridDim  = dim3(1, 1, 1);
    cfg.blockDim = dim3(32, 1, 1);
    cfg.dynamicSmemBytes = 0;
    cfg.stream = 0;
    cudaLaunchAttribute attr;
    attr.id = cudaLaunchAttributeProgrammaticStreamSerialization;
    attr.val.programmaticStreamSerializationAllowed = 1;
    cfg.attrs = &attr;
    cfg.numAttrs = 1;

    float neg_inv_n = -1.0f / (float)N;
    cudaLaunchKernelEx(&cfg, finalize_kernel, out, neg_inv_n);
}